// round 14
// baseline (speedup 1.0000x reference)
#include <cuda_runtime.h>
#include <cuda_fp16.h>
#include <cstdint>

// ---------------- problem constants ----------------
constexpr int Bn = 4, Tn = 1024, Hn = 2048, Vn = 32000;
constexpr int TOK = Bn * Tn;            // 4096 tokens
constexpr int M_TILE = 128;
constexpr int N_TILE = 128;
constexpr int K_CHUNK = 64;
constexpr int MTILES = TOK / M_TILE;    // 32
constexpr int NTILES = Vn / N_TILE;     // 250
constexpr int KITERS = Hn / K_CHUNK;    // 32
constexpr int STAGES = 3;

constexpr int TILES_PER_MODEL = MTILES * NTILES;   // 8000
constexpr int TOTAL_TILES = 2 * TILES_PER_MODEL;   // 16000

// smem row: 64 halves + 8 pad = 72 halves (144 B) -> conflict-free ldmatrix
constexpr int SROW = 72;
constexpr uint32_t BUF_A = M_TILE * SROW * 2;          // 18432 B
constexpr uint32_t BUF_B = N_TILE * SROW * 2;          // 18432 B
constexpr uint32_t STAGE = BUF_A + BUF_B;              // 36864 B
constexpr uint32_t SMEM_BYTES = STAGES * STAGE;        // 110592 B per CTA

// convert partition: 5120 blocks total
constexpr int CVT_W_BLOCKS = 2048;   // per weight array
constexpr int CVT_X_BLOCKS = 512;    // per activation array
constexpr int CVT_BLOCKS = 2 * CVT_W_BLOCKS + 2 * CVT_X_BLOCKS;  // 5120

// ---------------- device scratch (no runtime alloc allowed) ----------------
__device__ __half g_wh[2][(size_t)Vn * Hn];   // fp16 weights (policy, ref)
__device__ __half g_xh[2][(size_t)TOK * Hn];  // fp16 activations
__device__ float  g_partial[2][NTILES][TOK];  // per-ntile partial sumexp
__device__ float  g_sel[2][TOK];              // selected logits
__device__ float  g_logp[2][TOK];             // per-token logps

// ---------------- PTX helpers (baseline features only) ----------------
__device__ __forceinline__ uint32_t smem_u32(const void* p) {
    uint32_t a;
    asm("{ .reg .u64 t; cvta.to.shared.u64 t, %1; cvt.u32.u64 %0, t; }" : "=r"(a) : "l"(p));
    return a;
}

__device__ __forceinline__ void cp_async16(uint32_t dst, const void* src) {
    asm volatile("cp.async.cg.shared.global [%0], [%1], 16;" :: "r"(dst), "l"(src) : "memory");
}
#define CP_COMMIT() asm volatile("cp.async.commit_group;" ::: "memory")

__device__ __forceinline__ void ldsm_x4(uint32_t& r0, uint32_t& r1, uint32_t& r2, uint32_t& r3,
                                        uint32_t addr) {
    asm volatile("ldmatrix.sync.aligned.m8n8.x4.shared.b16 {%0,%1,%2,%3}, [%4];"
                 : "=r"(r0), "=r"(r1), "=r"(r2), "=r"(r3) : "r"(addr));
}

__device__ __forceinline__ void mma16816(float& d0, float& d1, float& d2, float& d3,
                                         uint32_t a0, uint32_t a1, uint32_t a2, uint32_t a3,
                                         uint32_t b0, uint32_t b1) {
    asm volatile(
        "mma.sync.aligned.m16n8k16.row.col.f32.f16.f16.f32 "
        "{%0,%1,%2,%3}, {%4,%5,%6,%7}, {%8,%9}, {%0,%1,%2,%3};"
        : "+f"(d0), "+f"(d1), "+f"(d2), "+f"(d3)
        : "r"(a0), "r"(a1), "r"(a2), "r"(a3), "r"(b0), "r"(b1));
}

// ---------------- fused convert kernel (block-range partitioned, no inner branch) ----
__device__ __forceinline__ void cvt_range(const float* __restrict__ src,
                                          __half* __restrict__ dst,
                                          int n4, int bstart, int nblocks) {
    int i = (blockIdx.x - bstart) * 256 + threadIdx.x;
    const int stride = nblocks * 256;
    for (; i < n4; i += stride) {
        float4 v = reinterpret_cast<const float4*>(src)[i];
        __half2 lo = __floats2half2_rn(v.x, v.y);
        __half2 hi = __floats2half2_rn(v.z, v.w);
        uint2 o;
        o.x = reinterpret_cast<uint32_t&>(lo);
        o.y = reinterpret_cast<uint32_t&>(hi);
        reinterpret_cast<uint2*>(dst)[i] = o;
    }
}

__global__ void convert_fused_kernel(const float* __restrict__ w, const float* __restrict__ rw,
                                     const float* __restrict__ x, const float* __restrict__ rx) {
    constexpr int NW = Vn * Hn / 4;
    constexpr int NX = TOK * Hn / 4;
    const int b = blockIdx.x;
    if (b < CVT_W_BLOCKS) {
        cvt_range(w, g_wh[0], NW, 0, CVT_W_BLOCKS);
    } else if (b < 2 * CVT_W_BLOCKS) {
        cvt_range(rw, g_wh[1], NW, CVT_W_BLOCKS, CVT_W_BLOCKS);
    } else if (b < 2 * CVT_W_BLOCKS + CVT_X_BLOCKS) {
        cvt_range(x, g_xh[0], NX, 2 * CVT_W_BLOCKS, CVT_X_BLOCKS);
    } else {
        cvt_range(rx, g_xh[1], NX, 2 * CVT_W_BLOCKS + CVT_X_BLOCKS, CVT_X_BLOCKS);
    }
}

// ---------------- GEMM tile body (champion mainloop, unchanged) ----------------
__device__ __forceinline__ void gemm_tile(char* dsm, int gz, int mt, int nt,
                                          const int* __restrict__ sel_ids) {
    const uint32_t sbase = smem_u32(dsm);
    const int tid = threadIdx.x;
    const int lane = tid & 31;
    const int wid = tid >> 5;
    const int warpM = wid >> 2;   // 0..1  (64 rows each)
    const int warpN = wid & 3;    // 0..3  (32 cols each)
    const int m0 = mt * M_TILE;
    const int n0 = nt * N_TILE;

    const __half* __restrict__ X = g_xh[gz];
    const __half* __restrict__ W = g_wh[gz];

    auto issue_load = [&](int p, int ki) {
        const __half* xg = X + (size_t)m0 * Hn + ki * K_CHUNK;
        const __half* wg = W + (size_t)n0 * Hn + ki * K_CHUNK;
        const uint32_t a_dst = sbase + p * STAGE;
        const uint32_t b_dst = a_dst + BUF_A;
#pragma unroll
        for (int j = 0; j < 4; j++) {
            int id = tid + j * 256;
            int r = id >> 3, c = id & 7;
            cp_async16(a_dst + r * (SROW * 2) + c * 16, xg + (size_t)r * Hn + c * 8);
        }
#pragma unroll
        for (int j = 0; j < 4; j++) {
            int id = tid + j * 256;
            int r = id >> 3, c = id & 7;
            cp_async16(b_dst + r * (SROW * 2) + c * 16, wg + (size_t)r * Hn + c * 8);
        }
        CP_COMMIT();
    };

    float acc[4][4][4];
#pragma unroll
    for (int mf = 0; mf < 4; mf++)
#pragma unroll
        for (int nf = 0; nf < 4; nf++)
#pragma unroll
            for (int k = 0; k < 4; k++) acc[mf][nf][k] = 0.f;

    const uint32_t a_lane_off =
        (uint32_t)((warpM * 64 + (lane & 15)) * (SROW * 2) + (lane >> 4) * 16);
    const int b_grp = lane >> 3, b_rw = lane & 7;
    const uint32_t b_lane_off = BUF_A +
        (uint32_t)((warpN * 32 + ((b_grp & 2) ? 8 : 0) + b_rw) * (SROW * 2) +
                   ((b_grp & 1) ? 16 : 0));

    issue_load(0, 0);
    issue_load(1, 1);

#pragma unroll 1
    for (int i = 0; i < KITERS; i++) {
        if (i + 1 < KITERS) asm volatile("cp.async.wait_group 1;" ::: "memory");
        else                asm volatile("cp.async.wait_group 0;" ::: "memory");
        __syncthreads();   // stage i visible; all warps finished compute(i-1)

        const uint32_t stage_base = sbase + (i % STAGES) * STAGE;

        // ks = 0: fragments first (critical path), then hide cp.async under MMAs
        {
            uint32_t a[4][4], b[2][4];
#pragma unroll
            for (int mf = 0; mf < 4; mf++)
                ldsm_x4(a[mf][0], a[mf][1], a[mf][2], a[mf][3],
                        stage_base + a_lane_off + mf * 16 * (SROW * 2));
#pragma unroll
            for (int nf2 = 0; nf2 < 2; nf2++)
                ldsm_x4(b[nf2][0], b[nf2][1], b[nf2][2], b[nf2][3],
                        stage_base + b_lane_off + nf2 * 16 * (SROW * 2));

            if (i + 2 < KITERS) issue_load((i + 2) % STAGES, i + 2);

#pragma unroll
            for (int mf = 0; mf < 4; mf++)
#pragma unroll
                for (int nf2 = 0; nf2 < 2; nf2++) {
                    mma16816(acc[mf][nf2 * 2][0], acc[mf][nf2 * 2][1],
                             acc[mf][nf2 * 2][2], acc[mf][nf2 * 2][3],
                             a[mf][0], a[mf][1], a[mf][2], a[mf][3],
                             b[nf2][0], b[nf2][1]);
                    mma16816(acc[mf][nf2 * 2 + 1][0], acc[mf][nf2 * 2 + 1][1],
                             acc[mf][nf2 * 2 + 1][2], acc[mf][nf2 * 2 + 1][3],
                             a[mf][0], a[mf][1], a[mf][2], a[mf][3],
                             b[nf2][2], b[nf2][3]);
                }
        }

#pragma unroll
        for (int ks = 1; ks < 4; ks++) {
            uint32_t a[4][4], b[2][4];
#pragma unroll
            for (int mf = 0; mf < 4; mf++)
                ldsm_x4(a[mf][0], a[mf][1], a[mf][2], a[mf][3],
                        stage_base + a_lane_off + mf * 16 * (SROW * 2) + ks * 32);
#pragma unroll
            for (int nf2 = 0; nf2 < 2; nf2++)
                ldsm_x4(b[nf2][0], b[nf2][1], b[nf2][2], b[nf2][3],
                        stage_base + b_lane_off + nf2 * 16 * (SROW * 2) + ks * 32);
#pragma unroll
            for (int mf = 0; mf < 4; mf++)
#pragma unroll
                for (int nf2 = 0; nf2 < 2; nf2++) {
                    mma16816(acc[mf][nf2 * 2][0], acc[mf][nf2 * 2][1],
                             acc[mf][nf2 * 2][2], acc[mf][nf2 * 2][3],
                             a[mf][0], a[mf][1], a[mf][2], a[mf][3],
                             b[nf2][0], b[nf2][1]);
                    mma16816(acc[mf][nf2 * 2 + 1][0], acc[mf][nf2 * 2 + 1][1],
                             acc[mf][nf2 * 2 + 1][2], acc[mf][nf2 * 2 + 1][3],
                             a[mf][0], a[mf][1], a[mf][2], a[mf][3],
                             b[nf2][2], b[nf2][3]);
                }
        }
    }

    // ---- epilogue: exp + row sums + selected-logit capture ----
    __syncthreads();
    float* rsum = reinterpret_cast<float*>(dsm);   // [4 warpN][128 rows]
    const int gq = lane >> 2;  // 0..7
#pragma unroll
    for (int mf = 0; mf < 4; mf++) {
        const int row0 = warpM * 64 + mf * 16 + gq;
        const int row1 = row0 + 8;
        const int sid0 = sel_ids[m0 + row0];
        const int sid1 = sel_ids[m0 + row1];
        float se0 = 0.f, se1 = 0.f;
#pragma unroll
        for (int nf = 0; nf < 4; nf++) {
            const float v0 = acc[mf][nf][0], v1 = acc[mf][nf][1];
            const float v2 = acc[mf][nf][2], v3 = acc[mf][nf][3];
            const int colb = n0 + warpN * 32 + nf * 8 + (lane & 3) * 2;
            se0 += __expf(v0) + __expf(v1);
            se1 += __expf(v2) + __expf(v3);
            if (colb == sid0)     g_sel[gz][m0 + row0] = v0;
            if (colb + 1 == sid0) g_sel[gz][m0 + row0] = v1;
            if (colb == sid1)     g_sel[gz][m0 + row1] = v2;
            if (colb + 1 == sid1) g_sel[gz][m0 + row1] = v3;
        }
        se0 += __shfl_xor_sync(0xFFFFFFFF, se0, 1);
        se0 += __shfl_xor_sync(0xFFFFFFFF, se0, 2);
        se1 += __shfl_xor_sync(0xFFFFFFFF, se1, 1);
        se1 += __shfl_xor_sync(0xFFFFFFFF, se1, 2);
        if ((lane & 3) == 0) {
            rsum[warpN * M_TILE + row0] = se0;
            rsum[warpN * M_TILE + row1] = se1;
        }
    }
    __syncthreads();
    if (tid < M_TILE) {
        g_partial[gz][nt][m0 + tid] = rsum[0 * M_TILE + tid] + rsum[1 * M_TILE + tid] +
                                      rsum[2 * M_TILE + tid] + rsum[3 * M_TILE + tid];
    }
}

// ---------------- merged GEMM kernel: both models, one launch ----------------
__global__ void __launch_bounds__(256, 2) gemm_all_kernel(const int* __restrict__ sel_ids) {
    extern __shared__ __align__(16) char dsm[];
    const int gid = blockIdx.x;                 // 0..15999
    const int gz = (gid >= TILES_PER_MODEL) ? 1 : 0;
    const int t = gid - gz * TILES_PER_MODEL;   // 0..7999
    const int mt = t & (MTILES - 1);            // mtile fastest (W-tile L2 sharing)
    const int nt = t >> 5;
    gemm_tile(dsm, gz, mt, nt, sel_ids);
}

// ---------------- per-token LSE / logp ----------------
__global__ void lse_kernel() {
    const int idx = blockIdx.x * blockDim.x + threadIdx.x;
    if (idx >= 2 * TOK) return;
    const int g = idx / TOK;
    const int t = idx % TOK;
    float s = 0.f;
#pragma unroll 5
    for (int nt = 0; nt < NTILES; nt++) s += g_partial[g][nt][t];
    g_logp[g][t] = g_sel[g][t] - logf(s);
}

// ---------------- final scalar loss ----------------
__global__ void loss_kernel(const int* __restrict__ mask,
                            const float* __restrict__ adv,
                            const float* __restrict__ oldlp,
                            float* __restrict__ out) {
    __shared__ double sh[1024], shm[1024];
    double acc = 0.0, macc = 0.0;
    for (int t = threadIdx.x; t < TOK; t += 1024) {
        const float per = g_logp[0][t];
        const float ref = g_logp[1][t];
        const float old = oldlp[t];
        const float a = adv[t / Tn];
        const float c1 = expf(per - old);
        const float c2 = fminf(fmaxf(c1, 1.0f - 0.2f), 1.0f + 0.2f);
        const float pl = -fminf(c1 * a, c2 * a);
        const float d = ref - per;
        const float kl = expf(d) - d - 1.0f;
        const float m = (float)mask[t];
        acc += (double)((pl + 0.1f * kl) * m);
        macc += (double)m;
    }
    sh[threadIdx.x] = acc;
    shm[threadIdx.x] = macc;
    __syncthreads();
    for (int s = 512; s > 0; s >>= 1) {
        if (threadIdx.x < s) {
            sh[threadIdx.x] += sh[threadIdx.x + s];
            shm[threadIdx.x] += shm[threadIdx.x + s];
        }
        __syncthreads();
    }
    if (threadIdx.x == 0) out[0] = (float)(sh[0] / fmax(shm[0], 1.0));
}

// ---------------- launch ----------------
extern "C" void kernel_launch(void* const* d_in, const int* in_sizes, int n_in,
                              void* d_out, int out_size) {
    const float* x     = (const float*)d_in[0];
    const float* rx    = (const float*)d_in[1];
    const float* w     = (const float*)d_in[2];
    const float* rw    = (const float*)d_in[3];
    const int*   sel   = (const int*)d_in[4];
    const int*   mask  = (const int*)d_in[5];
    const float* adv   = (const float*)d_in[6];
    const float* oldlp = (const float*)d_in[7];
    float* out = (float*)d_out;

    cudaFuncSetAttribute(gemm_all_kernel, cudaFuncAttributeMaxDynamicSharedMemorySize, SMEM_BYTES);

    convert_fused_kernel<<<CVT_BLOCKS, 256>>>(w, rw, x, rx);
    gemm_all_kernel<<<TOTAL_TILES, 256, SMEM_BYTES>>>(sel);
    lse_kernel<<<(2 * TOK + 255) / 256, 256>>>();
    loss_kernel<<<1, 1024>>>(mask, adv, oldlp, out);
}

// round 15
// speedup vs baseline: 1.0040x; 1.0040x over previous
#include <cuda_runtime.h>
#include <cuda_fp16.h>
#include <cstdint>

// ---------------- problem constants ----------------
constexpr int Bn = 4, Tn = 1024, Hn = 2048, Vn = 32000;
constexpr int TOK = Bn * Tn;            // 4096 tokens
constexpr int M_TILE = 128;
constexpr int N_TILE = 128;
constexpr int K_CHUNK = 64;
constexpr int MTILES = TOK / M_TILE;    // 32
constexpr int NTILES = Vn / N_TILE;     // 250
constexpr int KITERS = Hn / K_CHUNK;    // 32
constexpr int STAGES = 3;

constexpr int TILES_PER_MODEL = MTILES * NTILES;   // 8000
constexpr int TOTAL_TILES = 2 * TILES_PER_MODEL;   // 16000

// smem row: 64 halves + 8 pad = 72 halves (144 B) -> conflict-free ldmatrix
constexpr int SROW = 72;
constexpr uint32_t BUF_A = M_TILE * SROW * 2;          // 18432 B
constexpr uint32_t BUF_B = N_TILE * SROW * 2;          // 18432 B
constexpr uint32_t STAGE = BUF_A + BUF_B;              // 36864 B
constexpr uint32_t SMEM_BYTES = STAGES * STAGE;        // 110592 B per CTA

// convert partition: 5120 blocks total
constexpr int CVT_W_BLOCKS = 2048;   // per weight array
constexpr int CVT_X_BLOCKS = 512;    // per activation array
constexpr int CVT_BLOCKS = 2 * CVT_W_BLOCKS + 2 * CVT_X_BLOCKS;  // 5120

constexpr int LOSS_BLOCKS = 16;      // 16 x 256 threads = 4096 tokens

// ---------------- device scratch (no runtime alloc allowed) ----------------
__device__ __half g_wh[2][(size_t)Vn * Hn];   // fp16 weights (policy, ref)
__device__ __half g_xh[2][(size_t)TOK * Hn];  // fp16 activations
__device__ float  g_partial[2][NTILES][TOK];  // per-ntile partial sumexp
__device__ float  g_sel[2][TOK];              // selected logits
__device__ double g_bacc[LOSS_BLOCKS];        // per-block loss partials
__device__ double g_bmacc[LOSS_BLOCKS];       // per-block mask partials

// ---------------- PTX helpers (baseline features only) ----------------
__device__ __forceinline__ uint32_t smem_u32(const void* p) {
    uint32_t a;
    asm("{ .reg .u64 t; cvta.to.shared.u64 t, %1; cvt.u32.u64 %0, t; }" : "=r"(a) : "l"(p));
    return a;
}

__device__ __forceinline__ void cp_async16(uint32_t dst, const void* src) {
    asm volatile("cp.async.cg.shared.global [%0], [%1], 16;" :: "r"(dst), "l"(src) : "memory");
}
#define CP_COMMIT() asm volatile("cp.async.commit_group;" ::: "memory")

__device__ __forceinline__ void ldsm_x4(uint32_t& r0, uint32_t& r1, uint32_t& r2, uint32_t& r3,
                                        uint32_t addr) {
    asm volatile("ldmatrix.sync.aligned.m8n8.x4.shared.b16 {%0,%1,%2,%3}, [%4];"
                 : "=r"(r0), "=r"(r1), "=r"(r2), "=r"(r3) : "r"(addr));
}

__device__ __forceinline__ void mma16816(float& d0, float& d1, float& d2, float& d3,
                                         uint32_t a0, uint32_t a1, uint32_t a2, uint32_t a3,
                                         uint32_t b0, uint32_t b1) {
    asm volatile(
        "mma.sync.aligned.m16n8k16.row.col.f32.f16.f16.f32 "
        "{%0,%1,%2,%3}, {%4,%5,%6,%7}, {%8,%9}, {%0,%1,%2,%3};"
        : "+f"(d0), "+f"(d1), "+f"(d2), "+f"(d3)
        : "r"(a0), "r"(a1), "r"(a2), "r"(a3), "r"(b0), "r"(b1));
}

// ---------------- fused convert kernel (block-range partitioned) ----------------
__device__ __forceinline__ void cvt_range(const float* __restrict__ src,
                                          __half* __restrict__ dst,
                                          int n4, int bstart, int nblocks) {
    int i = (blockIdx.x - bstart) * 256 + threadIdx.x;
    const int stride = nblocks * 256;
    for (; i < n4; i += stride) {
        float4 v = reinterpret_cast<const float4*>(src)[i];
        __half2 lo = __floats2half2_rn(v.x, v.y);
        __half2 hi = __floats2half2_rn(v.z, v.w);
        uint2 o;
        o.x = reinterpret_cast<uint32_t&>(lo);
        o.y = reinterpret_cast<uint32_t&>(hi);
        reinterpret_cast<uint2*>(dst)[i] = o;
    }
}

__global__ void convert_fused_kernel(const float* __restrict__ w, const float* __restrict__ rw,
                                     const float* __restrict__ x, const float* __restrict__ rx) {
    constexpr int NW = Vn * Hn / 4;
    constexpr int NX = TOK * Hn / 4;
    const int b = blockIdx.x;
    if (b < CVT_W_BLOCKS) {
        cvt_range(w, g_wh[0], NW, 0, CVT_W_BLOCKS);
    } else if (b < 2 * CVT_W_BLOCKS) {
        cvt_range(rw, g_wh[1], NW, CVT_W_BLOCKS, CVT_W_BLOCKS);
    } else if (b < 2 * CVT_W_BLOCKS + CVT_X_BLOCKS) {
        cvt_range(x, g_xh[0], NX, 2 * CVT_W_BLOCKS, CVT_X_BLOCKS);
    } else {
        cvt_range(rx, g_xh[1], NX, 2 * CVT_W_BLOCKS + CVT_X_BLOCKS, CVT_X_BLOCKS);
    }
}

// ---------------- GEMM tile body (champion mainloop, unchanged) ----------------
__device__ __forceinline__ void gemm_tile(char* dsm, int gz, int mt, int nt,
                                          const int* __restrict__ sel_ids) {
    const uint32_t sbase = smem_u32(dsm);
    const int tid = threadIdx.x;
    const int lane = tid & 31;
    const int wid = tid >> 5;
    const int warpM = wid >> 2;   // 0..1  (64 rows each)
    const int warpN = wid & 3;    // 0..3  (32 cols each)
    const int m0 = mt * M_TILE;
    const int n0 = nt * N_TILE;

    const __half* __restrict__ X = g_xh[gz];
    const __half* __restrict__ W = g_wh[gz];

    auto issue_load = [&](int p, int ki) {
        const __half* xg = X + (size_t)m0 * Hn + ki * K_CHUNK;
        const __half* wg = W + (size_t)n0 * Hn + ki * K_CHUNK;
        const uint32_t a_dst = sbase + p * STAGE;
        const uint32_t b_dst = a_dst + BUF_A;
#pragma unroll
        for (int j = 0; j < 4; j++) {
            int id = tid + j * 256;
            int r = id >> 3, c = id & 7;
            cp_async16(a_dst + r * (SROW * 2) + c * 16, xg + (size_t)r * Hn + c * 8);
        }
#pragma unroll
        for (int j = 0; j < 4; j++) {
            int id = tid + j * 256;
            int r = id >> 3, c = id & 7;
            cp_async16(b_dst + r * (SROW * 2) + c * 16, wg + (size_t)r * Hn + c * 8);
        }
        CP_COMMIT();
    };

    float acc[4][4][4];
#pragma unroll
    for (int mf = 0; mf < 4; mf++)
#pragma unroll
        for (int nf = 0; nf < 4; nf++)
#pragma unroll
            for (int k = 0; k < 4; k++) acc[mf][nf][k] = 0.f;

    const uint32_t a_lane_off =
        (uint32_t)((warpM * 64 + (lane & 15)) * (SROW * 2) + (lane >> 4) * 16);
    const int b_grp = lane >> 3, b_rw = lane & 7;
    const uint32_t b_lane_off = BUF_A +
        (uint32_t)((warpN * 32 + ((b_grp & 2) ? 8 : 0) + b_rw) * (SROW * 2) +
                   ((b_grp & 1) ? 16 : 0));

    issue_load(0, 0);
    issue_load(1, 1);

#pragma unroll 1
    for (int i = 0; i < KITERS; i++) {
        if (i + 1 < KITERS) asm volatile("cp.async.wait_group 1;" ::: "memory");
        else                asm volatile("cp.async.wait_group 0;" ::: "memory");
        __syncthreads();   // stage i visible; all warps finished compute(i-1)

        const uint32_t stage_base = sbase + (i % STAGES) * STAGE;

        // ks = 0: fragments first (critical path), then hide cp.async under MMAs
        {
            uint32_t a[4][4], b[2][4];
#pragma unroll
            for (int mf = 0; mf < 4; mf++)
                ldsm_x4(a[mf][0], a[mf][1], a[mf][2], a[mf][3],
                        stage_base + a_lane_off + mf * 16 * (SROW * 2));
#pragma unroll
            for (int nf2 = 0; nf2 < 2; nf2++)
                ldsm_x4(b[nf2][0], b[nf2][1], b[nf2][2], b[nf2][3],
                        stage_base + b_lane_off + nf2 * 16 * (SROW * 2));

            if (i + 2 < KITERS) issue_load((i + 2) % STAGES, i + 2);

#pragma unroll
            for (int mf = 0; mf < 4; mf++)
#pragma unroll
                for (int nf2 = 0; nf2 < 2; nf2++) {
                    mma16816(acc[mf][nf2 * 2][0], acc[mf][nf2 * 2][1],
                             acc[mf][nf2 * 2][2], acc[mf][nf2 * 2][3],
                             a[mf][0], a[mf][1], a[mf][2], a[mf][3],
                             b[nf2][0], b[nf2][1]);
                    mma16816(acc[mf][nf2 * 2 + 1][0], acc[mf][nf2 * 2 + 1][1],
                             acc[mf][nf2 * 2 + 1][2], acc[mf][nf2 * 2 + 1][3],
                             a[mf][0], a[mf][1], a[mf][2], a[mf][3],
                             b[nf2][2], b[nf2][3]);
                }
        }

#pragma unroll
        for (int ks = 1; ks < 4; ks++) {
            uint32_t a[4][4], b[2][4];
#pragma unroll
            for (int mf = 0; mf < 4; mf++)
                ldsm_x4(a[mf][0], a[mf][1], a[mf][2], a[mf][3],
                        stage_base + a_lane_off + mf * 16 * (SROW * 2) + ks * 32);
#pragma unroll
            for (int nf2 = 0; nf2 < 2; nf2++)
                ldsm_x4(b[nf2][0], b[nf2][1], b[nf2][2], b[nf2][3],
                        stage_base + b_lane_off + nf2 * 16 * (SROW * 2) + ks * 32);
#pragma unroll
            for (int mf = 0; mf < 4; mf++)
#pragma unroll
                for (int nf2 = 0; nf2 < 2; nf2++) {
                    mma16816(acc[mf][nf2 * 2][0], acc[mf][nf2 * 2][1],
                             acc[mf][nf2 * 2][2], acc[mf][nf2 * 2][3],
                             a[mf][0], a[mf][1], a[mf][2], a[mf][3],
                             b[nf2][0], b[nf2][1]);
                    mma16816(acc[mf][nf2 * 2 + 1][0], acc[mf][nf2 * 2 + 1][1],
                             acc[mf][nf2 * 2 + 1][2], acc[mf][nf2 * 2 + 1][3],
                             a[mf][0], a[mf][1], a[mf][2], a[mf][3],
                             b[nf2][2], b[nf2][3]);
                }
        }
    }

    // ---- epilogue: exp + row sums + selected-logit capture ----
    __syncthreads();
    float* rsum = reinterpret_cast<float*>(dsm);   // [4 warpN][128 rows]
    const int gq = lane >> 2;  // 0..7
#pragma unroll
    for (int mf = 0; mf < 4; mf++) {
        const int row0 = warpM * 64 + mf * 16 + gq;
        const int row1 = row0 + 8;
        const int sid0 = sel_ids[m0 + row0];
        const int sid1 = sel_ids[m0 + row1];
        float se0 = 0.f, se1 = 0.f;
#pragma unroll
        for (int nf = 0; nf < 4; nf++) {
            const float v0 = acc[mf][nf][0], v1 = acc[mf][nf][1];
            const float v2 = acc[mf][nf][2], v3 = acc[mf][nf][3];
            const int colb = n0 + warpN * 32 + nf * 8 + (lane & 3) * 2;
            se0 += __expf(v0) + __expf(v1);
            se1 += __expf(v2) + __expf(v3);
            if (colb == sid0)     g_sel[gz][m0 + row0] = v0;
            if (colb + 1 == sid0) g_sel[gz][m0 + row0] = v1;
            if (colb == sid1)     g_sel[gz][m0 + row1] = v2;
            if (colb + 1 == sid1) g_sel[gz][m0 + row1] = v3;
        }
        se0 += __shfl_xor_sync(0xFFFFFFFF, se0, 1);
        se0 += __shfl_xor_sync(0xFFFFFFFF, se0, 2);
        se1 += __shfl_xor_sync(0xFFFFFFFF, se1, 1);
        se1 += __shfl_xor_sync(0xFFFFFFFF, se1, 2);
        if ((lane & 3) == 0) {
            rsum[warpN * M_TILE + row0] = se0;
            rsum[warpN * M_TILE + row1] = se1;
        }
    }
    __syncthreads();
    if (tid < M_TILE) {
        g_partial[gz][nt][m0 + tid] = rsum[0 * M_TILE + tid] + rsum[1 * M_TILE + tid] +
                                      rsum[2 * M_TILE + tid] + rsum[3 * M_TILE + tid];
    }
}

// ---------------- merged GEMM kernel: both models, one launch ----------------
__global__ void __launch_bounds__(256, 2) gemm_all_kernel(const int* __restrict__ sel_ids) {
    extern __shared__ __align__(16) char dsm[];
    const int gid = blockIdx.x;                 // 0..15999
    const int gz = (gid >= TILES_PER_MODEL) ? 1 : 0;
    const int t = gid - gz * TILES_PER_MODEL;   // 0..7999
    const int mt = t & (MTILES - 1);            // mtile fastest (W-tile L2 sharing)
    const int nt = t >> 5;
    gemm_tile(dsm, gz, mt, nt, sel_ids);
}

// ---------------- fused LSE + loss (16 blocks x 256 threads, 1 token/thread) ----------
__global__ void lse_loss_kernel(const int* __restrict__ mask,
                                const float* __restrict__ adv,
                                const float* __restrict__ oldlp) {
    const int t = blockIdx.x * 256 + threadIdx.x;   // 0..4095
    float s0 = 0.f, s1 = 0.f;
#pragma unroll 5
    for (int nt = 0; nt < NTILES; nt++) {
        s0 += g_partial[0][nt][t];
        s1 += g_partial[1][nt][t];
    }
    const float per = g_sel[0][t] - logf(s0);
    const float ref = g_sel[1][t] - logf(s1);
    const float old = oldlp[t];
    const float a = adv[t / Tn];
    const float c1 = expf(per - old);
    const float c2 = fminf(fmaxf(c1, 1.0f - 0.2f), 1.0f + 0.2f);
    const float pl = -fminf(c1 * a, c2 * a);
    const float d = ref - per;
    const float kl = expf(d) - d - 1.0f;
    const float m = (float)mask[t];

    __shared__ double sh[256], shm[256];
    sh[threadIdx.x] = (double)((pl + 0.1f * kl) * m);
    shm[threadIdx.x] = (double)m;
    __syncthreads();
#pragma unroll
    for (int s = 128; s > 0; s >>= 1) {
        if (threadIdx.x < s) {
            sh[threadIdx.x] += sh[threadIdx.x + s];
            shm[threadIdx.x] += shm[threadIdx.x + s];
        }
        __syncthreads();
    }
    if (threadIdx.x == 0) {
        g_bacc[blockIdx.x] = sh[0];
        g_bmacc[blockIdx.x] = shm[0];
    }
}

// ---------------- finalize (fixed-order sum of 16 block partials) ----------------
__global__ void finalize_kernel(float* __restrict__ out) {
    double a = 0.0, mm = 0.0;
#pragma unroll
    for (int i = 0; i < LOSS_BLOCKS; i++) {
        a += g_bacc[i];
        mm += g_bmacc[i];
    }
    out[0] = (float)(a / fmax(mm, 1.0));
}

// ---------------- launch ----------------
extern "C" void kernel_launch(void* const* d_in, const int* in_sizes, int n_in,
                              void* d_out, int out_size) {
    const float* x     = (const float*)d_in[0];
    const float* rx    = (const float*)d_in[1];
    const float* w     = (const float*)d_in[2];
    const float* rw    = (const float*)d_in[3];
    const int*   sel   = (const int*)d_in[4];
    const int*   mask  = (const int*)d_in[5];
    const float* adv   = (const float*)d_in[6];
    const float* oldlp = (const float*)d_in[7];
    float* out = (float*)d_out;

    cudaFuncSetAttribute(gemm_all_kernel, cudaFuncAttributeMaxDynamicSharedMemorySize, SMEM_BYTES);

    convert_fused_kernel<<<CVT_BLOCKS, 256>>>(w, rw, x, rx);
    gemm_all_kernel<<<TOTAL_TILES, 256, SMEM_BYTES>>>(sel);
    lse_loss_kernel<<<LOSS_BLOCKS, 256>>>(mask, adv, oldlp);
    finalize_kernel<<<1, 1>>>(out);
}

// round 16
// speedup vs baseline: 1.0041x; 1.0001x over previous
#include <cuda_runtime.h>
#include <cuda_fp16.h>
#include <cstdint>

// ---------------- problem constants ----------------
constexpr int Bn = 4, Tn = 1024, Hn = 2048, Vn = 32000;
constexpr int TOK = Bn * Tn;            // 4096 tokens
constexpr int M_TILE = 128;
constexpr int N_TILE = 128;
constexpr int K_CHUNK = 64;
constexpr int MTILES = TOK / M_TILE;    // 32
constexpr int NTILES = Vn / N_TILE;     // 250
constexpr int KITERS = Hn / K_CHUNK;    // 32
constexpr int STAGES = 3;

constexpr int TILES_PER_MODEL = MTILES * NTILES;   // 8000
constexpr int TOTAL_TILES = 2 * TILES_PER_MODEL;   // 16000

// smem row: 64 halves + 8 pad = 72 halves (144 B) -> conflict-free ldmatrix
constexpr int SROW = 72;
constexpr uint32_t BUF_A = M_TILE * SROW * 2;          // 18432 B
constexpr uint32_t BUF_B = N_TILE * SROW * 2;          // 18432 B
constexpr uint32_t STAGE = BUF_A + BUF_B;              // 36864 B
constexpr uint32_t SMEM_BYTES = STAGES * STAGE;        // 110592 B per CTA

// convert partition: 5120 blocks total
constexpr int CVT_W_BLOCKS = 2048;   // per weight array
constexpr int CVT_X_BLOCKS = 512;    // per activation array
constexpr int CVT_BLOCKS = 2 * CVT_W_BLOCKS + 2 * CVT_X_BLOCKS;  // 5120

constexpr int LOSS_BLOCKS = 32;      // 32 x 128 threads = 4096 tokens

// ---------------- device scratch (no runtime alloc allowed) ----------------
__device__ __half g_wh[2][(size_t)Vn * Hn];   // fp16 weights (policy, ref)
__device__ __half g_xh[2][(size_t)TOK * Hn];  // fp16 activations
__device__ float  g_partial[2][NTILES][TOK];  // per-ntile partial sumexp
__device__ float  g_sel[2][TOK];              // selected logits
__device__ double g_bacc[LOSS_BLOCKS];        // per-block loss partials
__device__ double g_bmacc[LOSS_BLOCKS];       // per-block mask partials

// ---------------- PTX helpers (baseline features only) ----------------
__device__ __forceinline__ uint32_t smem_u32(const void* p) {
    uint32_t a;
    asm("{ .reg .u64 t; cvta.to.shared.u64 t, %1; cvt.u32.u64 %0, t; }" : "=r"(a) : "l"(p));
    return a;
}

__device__ __forceinline__ void cp_async16(uint32_t dst, const void* src) {
    asm volatile("cp.async.cg.shared.global [%0], [%1], 16;" :: "r"(dst), "l"(src) : "memory");
}
#define CP_COMMIT() asm volatile("cp.async.commit_group;" ::: "memory")

__device__ __forceinline__ void ldsm_x4(uint32_t& r0, uint32_t& r1, uint32_t& r2, uint32_t& r3,
                                        uint32_t addr) {
    asm volatile("ldmatrix.sync.aligned.m8n8.x4.shared.b16 {%0,%1,%2,%3}, [%4];"
                 : "=r"(r0), "=r"(r1), "=r"(r2), "=r"(r3) : "r"(addr));
}

__device__ __forceinline__ void mma16816(float& d0, float& d1, float& d2, float& d3,
                                         uint32_t a0, uint32_t a1, uint32_t a2, uint32_t a3,
                                         uint32_t b0, uint32_t b1) {
    asm volatile(
        "mma.sync.aligned.m16n8k16.row.col.f32.f16.f16.f32 "
        "{%0,%1,%2,%3}, {%4,%5,%6,%7}, {%8,%9}, {%0,%1,%2,%3};"
        : "+f"(d0), "+f"(d1), "+f"(d2), "+f"(d3)
        : "r"(a0), "r"(a1), "r"(a2), "r"(a3), "r"(b0), "r"(b1));
}

// ---------------- fused convert kernel (block-range partitioned) ----------------
__device__ __forceinline__ void cvt_range(const float* __restrict__ src,
                                          __half* __restrict__ dst,
                                          int n4, int bstart, int nblocks) {
    int i = (blockIdx.x - bstart) * 256 + threadIdx.x;
    const int stride = nblocks * 256;
    for (; i < n4; i += stride) {
        float4 v = reinterpret_cast<const float4*>(src)[i];
        __half2 lo = __floats2half2_rn(v.x, v.y);
        __half2 hi = __floats2half2_rn(v.z, v.w);
        uint2 o;
        o.x = reinterpret_cast<uint32_t&>(lo);
        o.y = reinterpret_cast<uint32_t&>(hi);
        reinterpret_cast<uint2*>(dst)[i] = o;
    }
}

__global__ void convert_fused_kernel(const float* __restrict__ w, const float* __restrict__ rw,
                                     const float* __restrict__ x, const float* __restrict__ rx) {
    constexpr int NW = Vn * Hn / 4;
    constexpr int NX = TOK * Hn / 4;
    const int b = blockIdx.x;
    if (b < CVT_W_BLOCKS) {
        cvt_range(w, g_wh[0], NW, 0, CVT_W_BLOCKS);
    } else if (b < 2 * CVT_W_BLOCKS) {
        cvt_range(rw, g_wh[1], NW, CVT_W_BLOCKS, CVT_W_BLOCKS);
    } else if (b < 2 * CVT_W_BLOCKS + CVT_X_BLOCKS) {
        cvt_range(x, g_xh[0], NX, 2 * CVT_W_BLOCKS, CVT_X_BLOCKS);
    } else {
        cvt_range(rx, g_xh[1], NX, 2 * CVT_W_BLOCKS + CVT_X_BLOCKS, CVT_X_BLOCKS);
    }
}

// ---------------- GEMM tile body (champion mainloop, unchanged) ----------------
__device__ __forceinline__ void gemm_tile(char* dsm, int gz, int mt, int nt,
                                          const int* __restrict__ sel_ids) {
    const uint32_t sbase = smem_u32(dsm);
    const int tid = threadIdx.x;
    const int lane = tid & 31;
    const int wid = tid >> 5;
    const int warpM = wid >> 2;   // 0..1  (64 rows each)
    const int warpN = wid & 3;    // 0..3  (32 cols each)
    const int m0 = mt * M_TILE;
    const int n0 = nt * N_TILE;

    const __half* __restrict__ X = g_xh[gz];
    const __half* __restrict__ W = g_wh[gz];

    auto issue_load = [&](int p, int ki) {
        const __half* xg = X + (size_t)m0 * Hn + ki * K_CHUNK;
        const __half* wg = W + (size_t)n0 * Hn + ki * K_CHUNK;
        const uint32_t a_dst = sbase + p * STAGE;
        const uint32_t b_dst = a_dst + BUF_A;
#pragma unroll
        for (int j = 0; j < 4; j++) {
            int id = tid + j * 256;
            int r = id >> 3, c = id & 7;
            cp_async16(a_dst + r * (SROW * 2) + c * 16, xg + (size_t)r * Hn + c * 8);
        }
#pragma unroll
        for (int j = 0; j < 4; j++) {
            int id = tid + j * 256;
            int r = id >> 3, c = id & 7;
            cp_async16(b_dst + r * (SROW * 2) + c * 16, wg + (size_t)r * Hn + c * 8);
        }
        CP_COMMIT();
    };

    float acc[4][4][4];
#pragma unroll
    for (int mf = 0; mf < 4; mf++)
#pragma unroll
        for (int nf = 0; nf < 4; nf++)
#pragma unroll
            for (int k = 0; k < 4; k++) acc[mf][nf][k] = 0.f;

    const uint32_t a_lane_off =
        (uint32_t)((warpM * 64 + (lane & 15)) * (SROW * 2) + (lane >> 4) * 16);
    const int b_grp = lane >> 3, b_rw = lane & 7;
    const uint32_t b_lane_off = BUF_A +
        (uint32_t)((warpN * 32 + ((b_grp & 2) ? 8 : 0) + b_rw) * (SROW * 2) +
                   ((b_grp & 1) ? 16 : 0));

    issue_load(0, 0);
    issue_load(1, 1);

#pragma unroll 1
    for (int i = 0; i < KITERS; i++) {
        if (i + 1 < KITERS) asm volatile("cp.async.wait_group 1;" ::: "memory");
        else                asm volatile("cp.async.wait_group 0;" ::: "memory");
        __syncthreads();   // stage i visible; all warps finished compute(i-1)

        const uint32_t stage_base = sbase + (i % STAGES) * STAGE;

        // ks = 0: fragments first (critical path), then hide cp.async under MMAs
        {
            uint32_t a[4][4], b[2][4];
#pragma unroll
            for (int mf = 0; mf < 4; mf++)
                ldsm_x4(a[mf][0], a[mf][1], a[mf][2], a[mf][3],
                        stage_base + a_lane_off + mf * 16 * (SROW * 2));
#pragma unroll
            for (int nf2 = 0; nf2 < 2; nf2++)
                ldsm_x4(b[nf2][0], b[nf2][1], b[nf2][2], b[nf2][3],
                        stage_base + b_lane_off + nf2 * 16 * (SROW * 2));

            if (i + 2 < KITERS) issue_load((i + 2) % STAGES, i + 2);

#pragma unroll
            for (int mf = 0; mf < 4; mf++)
#pragma unroll
                for (int nf2 = 0; nf2 < 2; nf2++) {
                    mma16816(acc[mf][nf2 * 2][0], acc[mf][nf2 * 2][1],
                             acc[mf][nf2 * 2][2], acc[mf][nf2 * 2][3],
                             a[mf][0], a[mf][1], a[mf][2], a[mf][3],
                             b[nf2][0], b[nf2][1]);
                    mma16816(acc[mf][nf2 * 2 + 1][0], acc[mf][nf2 * 2 + 1][1],
                             acc[mf][nf2 * 2 + 1][2], acc[mf][nf2 * 2 + 1][3],
                             a[mf][0], a[mf][1], a[mf][2], a[mf][3],
                             b[nf2][2], b[nf2][3]);
                }
        }

#pragma unroll
        for (int ks = 1; ks < 4; ks++) {
            uint32_t a[4][4], b[2][4];
#pragma unroll
            for (int mf = 0; mf < 4; mf++)
                ldsm_x4(a[mf][0], a[mf][1], a[mf][2], a[mf][3],
                        stage_base + a_lane_off + mf * 16 * (SROW * 2) + ks * 32);
#pragma unroll
            for (int nf2 = 0; nf2 < 2; nf2++)
                ldsm_x4(b[nf2][0], b[nf2][1], b[nf2][2], b[nf2][3],
                        stage_base + b_lane_off + nf2 * 16 * (SROW * 2) + ks * 32);
#pragma unroll
            for (int mf = 0; mf < 4; mf++)
#pragma unroll
                for (int nf2 = 0; nf2 < 2; nf2++) {
                    mma16816(acc[mf][nf2 * 2][0], acc[mf][nf2 * 2][1],
                             acc[mf][nf2 * 2][2], acc[mf][nf2 * 2][3],
                             a[mf][0], a[mf][1], a[mf][2], a[mf][3],
                             b[nf2][0], b[nf2][1]);
                    mma16816(acc[mf][nf2 * 2 + 1][0], acc[mf][nf2 * 2 + 1][1],
                             acc[mf][nf2 * 2 + 1][2], acc[mf][nf2 * 2 + 1][3],
                             a[mf][0], a[mf][1], a[mf][2], a[mf][3],
                             b[nf2][2], b[nf2][3]);
                }
        }
    }

    // ---- epilogue: exp + row sums + selected-logit capture ----
    __syncthreads();
    float* rsum = reinterpret_cast<float*>(dsm);   // [4 warpN][128 rows]
    const int gq = lane >> 2;  // 0..7
#pragma unroll
    for (int mf = 0; mf < 4; mf++) {
        const int row0 = warpM * 64 + mf * 16 + gq;
        const int row1 = row0 + 8;
        const int sid0 = sel_ids[m0 + row0];
        const int sid1 = sel_ids[m0 + row1];
        float se0 = 0.f, se1 = 0.f;
#pragma unroll
        for (int nf = 0; nf < 4; nf++) {
            const float v0 = acc[mf][nf][0], v1 = acc[mf][nf][1];
            const float v2 = acc[mf][nf][2], v3 = acc[mf][nf][3];
            const int colb = n0 + warpN * 32 + nf * 8 + (lane & 3) * 2;
            se0 += __expf(v0) + __expf(v1);
            se1 += __expf(v2) + __expf(v3);
            if (colb == sid0)     g_sel[gz][m0 + row0] = v0;
            if (colb + 1 == sid0) g_sel[gz][m0 + row0] = v1;
            if (colb == sid1)     g_sel[gz][m0 + row1] = v2;
            if (colb + 1 == sid1) g_sel[gz][m0 + row1] = v3;
        }
        se0 += __shfl_xor_sync(0xFFFFFFFF, se0, 1);
        se0 += __shfl_xor_sync(0xFFFFFFFF, se0, 2);
        se1 += __shfl_xor_sync(0xFFFFFFFF, se1, 1);
        se1 += __shfl_xor_sync(0xFFFFFFFF, se1, 2);
        if ((lane & 3) == 0) {
            rsum[warpN * M_TILE + row0] = se0;
            rsum[warpN * M_TILE + row1] = se1;
        }
    }
    __syncthreads();
    if (tid < M_TILE) {
        g_partial[gz][nt][m0 + tid] = rsum[0 * M_TILE + tid] + rsum[1 * M_TILE + tid] +
                                      rsum[2 * M_TILE + tid] + rsum[3 * M_TILE + tid];
    }
}

// ---------------- merged GEMM kernel: both models, one launch ----------------
__global__ void __launch_bounds__(256, 2) gemm_all_kernel(const int* __restrict__ sel_ids) {
    extern __shared__ __align__(16) char dsm[];
    const int gid = blockIdx.x;                 // 0..15999
    const int gz = (gid >= TILES_PER_MODEL) ? 1 : 0;
    const int t = gid - gz * TILES_PER_MODEL;   // 0..7999
    const int mt = t & (MTILES - 1);            // mtile fastest (W-tile L2 sharing)
    const int nt = t >> 5;
    gemm_tile(dsm, gz, mt, nt, sel_ids);
}

// ---------------- fused LSE + loss (32 blocks x 128 threads, 1 token/thread) ----------
__global__ void lse_loss_kernel(const int* __restrict__ mask,
                                const float* __restrict__ adv,
                                const float* __restrict__ oldlp) {
    const int t = blockIdx.x * 128 + threadIdx.x;   // 0..4095
    float s0 = 0.f, s1 = 0.f;
#pragma unroll 5
    for (int nt = 0; nt < NTILES; nt++) {
        s0 += g_partial[0][nt][t];
        s1 += g_partial[1][nt][t];
    }
    const float per = g_sel[0][t] - logf(s0);
    const float ref = g_sel[1][t] - logf(s1);
    const float old = oldlp[t];
    const float a = adv[t / Tn];
    const float c1 = expf(per - old);
    const float c2 = fminf(fmaxf(c1, 1.0f - 0.2f), 1.0f + 0.2f);
    const float pl = -fminf(c1 * a, c2 * a);
    const float d = ref - per;
    const float kl = expf(d) - d - 1.0f;
    const float m = (float)mask[t];

    __shared__ double sh[128], shm[128];
    sh[threadIdx.x] = (double)((pl + 0.1f * kl) * m);
    shm[threadIdx.x] = (double)m;
    __syncthreads();
#pragma unroll
    for (int s = 64; s > 0; s >>= 1) {
        if (threadIdx.x < s) {
            sh[threadIdx.x] += sh[threadIdx.x + s];
            shm[threadIdx.x] += shm[threadIdx.x + s];
        }
        __syncthreads();
    }
    if (threadIdx.x == 0) {
        g_bacc[blockIdx.x] = sh[0];
        g_bmacc[blockIdx.x] = shm[0];
    }
}

// ---------------- finalize: one warp, parallel loads + fixed butterfly ----------------
__global__ void finalize_kernel(float* __restrict__ out) {
    const int lane = threadIdx.x;   // 0..31
    double a = g_bacc[lane];
    double mm = g_bmacc[lane];
    // fixed-pattern butterfly: combine tree is compile-time deterministic
#pragma unroll
    for (int s = 16; s > 0; s >>= 1) {
        a  += __shfl_xor_sync(0xFFFFFFFF, a, s);
        mm += __shfl_xor_sync(0xFFFFFFFF, mm, s);
    }
    if (lane == 0) out[0] = (float)(a / fmax(mm, 1.0));
}

// ---------------- launch ----------------
extern "C" void kernel_launch(void* const* d_in, const int* in_sizes, int n_in,
                              void* d_out, int out_size) {
    const float* x     = (const float*)d_in[0];
    const float* rx    = (const float*)d_in[1];
    const float* w     = (const float*)d_in[2];
    const float* rw    = (const float*)d_in[3];
    const int*   sel   = (const int*)d_in[4];
    const int*   mask  = (const int*)d_in[5];
    const float* adv   = (const float*)d_in[6];
    const float* oldlp = (const float*)d_in[7];
    float* out = (float*)d_out;

    cudaFuncSetAttribute(gemm_all_kernel, cudaFuncAttributeMaxDynamicSharedMemorySize, SMEM_BYTES);

    convert_fused_kernel<<<CVT_BLOCKS, 256>>>(w, rw, x, rx);
    gemm_all_kernel<<<TOTAL_TILES, 256, SMEM_BYTES>>>(sel);
    lse_loss_kernel<<<LOSS_BLOCKS, 128>>>(mask, adv, oldlp);
    finalize_kernel<<<1, 32>>>(out);
}